// round 8
// baseline (speedup 1.0000x reference)
#include <cuda_runtime.h>
#include <cuda_bf16.h>
#include <cstdint>

// CycleEmbedding via code-count factorization:
//   out[c,:] = sum_k count[c,k] * emb[k,:],  count[c,k] = #{e: cycle_e=c, x[atom_e]=k}
// x: [100000] int32 (0..21), atom_to_cycle: [2, 600000] int32,
// emb_weight: [22,128] f32, out: [100000,128] f32.
//
// g_counts is zero-initialized at module load. expand_kernel restores every
// entry it reads back to zero (coalesced int4 stores), so the invariant
// "counts all zero at kernel_launch entry" holds across correctness run,
// capture, and every graph replay.

#define HIDDEN 128
#define NUM_CODES 22
#define MAX_SEGMENTS 100000
#define ROWS_PER_BLOCK 64
#define ETHREADS 512

__device__ int g_counts[MAX_SEGMENTS * NUM_CODES];   // 8.8 MB scratch, zero-init

__global__ void __launch_bounds__(256) count_kernel(
    const int* __restrict__ x,
    const int* __restrict__ atom_idx,
    const int* __restrict__ cycle_idx,
    int E4)                                 // number of 4-edge groups
{
    int g = blockIdx.x * blockDim.x + threadIdx.x;
    if (g >= E4) return;

    int4 a = __ldg(reinterpret_cast<const int4*>(atom_idx) + g);
    int4 c = __ldg(reinterpret_cast<const int4*>(cycle_idx) + g);

    int k0 = __ldg(&x[a.x]);
    int k1 = __ldg(&x[a.y]);
    int k2 = __ldg(&x[a.z]);
    int k3 = __ldg(&x[a.w]);

    atomicAdd(&g_counts[c.x * NUM_CODES + k0], 1);
    atomicAdd(&g_counts[c.y * NUM_CODES + k1], 1);
    atomicAdd(&g_counts[c.z * NUM_CODES + k2], 1);
    atomicAdd(&g_counts[c.w * NUM_CODES + k3], 1);
}

__global__ void __launch_bounds__(256) count_tail_kernel(
    const int* __restrict__ x,
    const int* __restrict__ atom_idx,
    const int* __restrict__ cycle_idx,
    int E)
{
    int e = blockIdx.x * blockDim.x + threadIdx.x;
    if (e >= E) return;
    int a = __ldg(&atom_idx[e]);
    int c = __ldg(&cycle_idx[e]);
    int code = __ldg(&x[a]);
    atomicAdd(&g_counts[c * NUM_CODES + code], 1);
}

__global__ void __launch_bounds__(ETHREADS) expand_kernel(
    const float* __restrict__ emb,       // [22, 128]
    float* __restrict__ out,             // [S, 128]
    int S)
{
    __shared__ float s_emb[NUM_CODES * HIDDEN];             // 11 KB
    __shared__ int   s_cnt[ROWS_PER_BLOCK * NUM_CODES];     // 5.5 KB
    __shared__ int2  s_terms[ROWS_PER_BLOCK * NUM_CODES];   // 11 KB: (emb byte off, countf bits)
    __shared__ int   s_nt[ROWS_PER_BLOCK];

    for (int i = threadIdx.x; i < NUM_CODES * HIDDEN; i += ETHREADS)
        s_emb[i] = emb[i];

    const int row0 = blockIdx.x * ROWS_PER_BLOCK;
    const int nrows = min(ROWS_PER_BLOCK, S - row0);
    const int ncnt = nrows * NUM_CODES;

    // stage counts (coalesced int4) and zero-restore in place.
    // base is int4-aligned: row0*22*4 bytes, row0 multiple of 64 -> mult of 16.
    int4* gc4 = reinterpret_cast<int4*>(&g_counts[row0 * NUM_CODES]);
    int4* sc4 = reinterpret_cast<int4*>(s_cnt);
    const int n4 = ncnt >> 2;
    for (int i = threadIdx.x; i < n4; i += ETHREADS) {
        sc4[i] = gc4[i];
        gc4[i] = make_int4(0, 0, 0, 0);
    }
    for (int i = (n4 << 2) + threadIdx.x; i < ncnt; i += ETHREADS) {
        s_cnt[i] = g_counts[row0 * NUM_CODES + i];
        g_counts[row0 * NUM_CODES + i] = 0;
    }
    __syncthreads();

    // build compact term lists: thread t handles row t
    if (threadIdx.x < nrows) {
        const int t = threadIdx.x;
        int nt = 0;
        #pragma unroll
        for (int k = 0; k < NUM_CODES; k++) {
            int c = s_cnt[t * NUM_CODES + k];
            if (c) {
                s_terms[t * NUM_CODES + nt] =
                    make_int2(k * (HIDDEN * 4), __float_as_int((float)c));
                nt++;
            }
        }
        s_nt[t] = nt;
    }
    __syncthreads();

    const int lane = threadIdx.x & 31;
    const int warp = threadIdx.x >> 5;                       // 0..15
    const char* const embb = (const char*)s_emb;
    const uint32_t lane_off = (uint32_t)lane << 4;
    float4* out4 = reinterpret_cast<float4*>(out);

    #pragma unroll
    for (int rr = 0; rr < ROWS_PER_BLOCK / 16; rr++) {       // 4 rows per warp
        int rl = warp * (ROWS_PER_BLOCK / 16) + rr;
        int row = row0 + rl;
        if (row >= S) break;

        int nt = s_nt[rl];                                   // broadcast LDS
        const int2* terms = &s_terms[rl * NUM_CODES];

        float4 acc = make_float4(0.f, 0.f, 0.f, 0.f);
        for (int j = 0; j < nt; j++) {
            int2 p = terms[j];                               // LDS.64 broadcast
            float f = __int_as_float(p.y);
            float4 e = *reinterpret_cast<const float4*>(embb + p.x + lane_off);
            acc.x += f * e.x; acc.y += f * e.y;
            acc.z += f * e.z; acc.w += f * e.w;
        }
        out4[(size_t)row * 32 + lane] = acc;
    }
}

extern "C" void kernel_launch(void* const* d_in, const int* in_sizes, int n_in,
                              void* d_out, int out_size)
{
    const int*   x   = (const int*)d_in[0];
    const int*   a2c = (const int*)d_in[1];
    const float* emb = (const float*)d_in[2];
    float*       out = (float*)d_out;

    const int E = in_sizes[1] / 2;                   // 600000
    const int S = out_size / HIDDEN;                 // 100000
    const int* atom_idx  = a2c;
    const int* cycle_idx = a2c + E;

    // 1) histogram edges into (cycle, code) counts, 4 edges/thread
    if ((E & 3) == 0) {
        int E4 = E >> 2;
        count_kernel<<<(E4 + 255) / 256, 256>>>(x, atom_idx, cycle_idx, E4);
    } else {
        count_tail_kernel<<<(E + 255) / 256, 256>>>(x, atom_idx, cycle_idx, E);
    }

    // 2) expand counts -> output rows (64 rows/block); also re-zeros counts
    expand_kernel<<<(S + ROWS_PER_BLOCK - 1) / ROWS_PER_BLOCK, ETHREADS>>>(emb, out, S);
}

// round 9
// speedup vs baseline: 1.0366x; 1.0366x over previous
#include <cuda_runtime.h>
#include <cuda_bf16.h>
#include <cstdint>

// CycleEmbedding via code-count factorization:
//   out[c,:] = sum_k count[c,k] * emb[k,:]
// x: [100000] int32 (0..21), atom_to_cycle: [2, 600000] int32,
// emb_weight: [22,128] f32, out: [100000,128] f32.
//
// g_counts zero-initialized at module load; expand_kernel restores every entry
// it reads to zero, so "all zero at kernel_launch entry" holds across the
// correctness run, capture, and every graph replay.

#define HIDDEN 128
#define NUM_CODES 22
#define MAX_SEGMENTS 100000
#define ROWS_PER_WARP 4
#define EWARPS 8
#define ETHREADS (EWARPS * 32)
#define ROWS_PER_BLOCK (EWARPS * ROWS_PER_WARP)   // 32

__device__ int g_counts[MAX_SEGMENTS * NUM_CODES];   // 8.8 MB scratch, zero-init

__global__ void __launch_bounds__(256) count_kernel(
    const int* __restrict__ x,
    const int* __restrict__ atom_idx,
    const int* __restrict__ cycle_idx,
    int E8)                                 // number of 8-edge groups
{
    int g = blockIdx.x * blockDim.x + threadIdx.x;
    if (g >= E8) return;

    const int4* a4 = reinterpret_cast<const int4*>(atom_idx) + g * 2;
    const int4* c4 = reinterpret_cast<const int4*>(cycle_idx) + g * 2;
    int4 a0 = __ldg(a4);     int4 a1 = __ldg(a4 + 1);
    int4 c0 = __ldg(c4);     int4 c1 = __ldg(c4 + 1);

    int k0 = __ldg(&x[a0.x]); int k1 = __ldg(&x[a0.y]);
    int k2 = __ldg(&x[a0.z]); int k3 = __ldg(&x[a0.w]);
    int k4 = __ldg(&x[a1.x]); int k5 = __ldg(&x[a1.y]);
    int k6 = __ldg(&x[a1.z]); int k7 = __ldg(&x[a1.w]);

    atomicAdd(&g_counts[c0.x * NUM_CODES + k0], 1);
    atomicAdd(&g_counts[c0.y * NUM_CODES + k1], 1);
    atomicAdd(&g_counts[c0.z * NUM_CODES + k2], 1);
    atomicAdd(&g_counts[c0.w * NUM_CODES + k3], 1);
    atomicAdd(&g_counts[c1.x * NUM_CODES + k4], 1);
    atomicAdd(&g_counts[c1.y * NUM_CODES + k5], 1);
    atomicAdd(&g_counts[c1.z * NUM_CODES + k6], 1);
    atomicAdd(&g_counts[c1.w * NUM_CODES + k7], 1);
}

__global__ void __launch_bounds__(256) count_tail_kernel(
    const int* __restrict__ x,
    const int* __restrict__ atom_idx,
    const int* __restrict__ cycle_idx,
    int start, int E)
{
    int e = start + blockIdx.x * blockDim.x + threadIdx.x;
    if (e >= E) return;
    int a = __ldg(&atom_idx[e]);
    int c = __ldg(&cycle_idx[e]);
    int code = __ldg(&x[a]);
    atomicAdd(&g_counts[c * NUM_CODES + code], 1);
}

__global__ void __launch_bounds__(ETHREADS, 4) expand_kernel(
    const float* __restrict__ emb,       // [22, 128]
    float* __restrict__ out,             // [S, 128]
    int S)
{
    __shared__ float s_emb[NUM_CODES * HIDDEN];           // 11 KB
    __shared__ int2  s_terms[ROWS_PER_BLOCK * NUM_CODES]; // 5.5 KB

    for (int i = threadIdx.x; i < NUM_CODES * HIDDEN; i += ETHREADS)
        s_emb[i] = emb[i];

    const int lane = threadIdx.x & 31;
    const int warp = threadIdx.x >> 5;                    // 0..7
    const int row_base = blockIdx.x * ROWS_PER_BLOCK + warp * ROWS_PER_WARP;
    const unsigned lt = (1u << lane) - 1u;

    // ---- build: 4 independent count loads issued upfront ----
    int cnt[ROWS_PER_WARP];
    #pragma unroll
    for (int r = 0; r < ROWS_PER_WARP; r++) {
        int row = row_base + r;
        cnt[r] = (lane < NUM_CODES && row < S)
                   ? __ldg(&g_counts[row * NUM_CODES + lane]) : 0;
    }

    int m = 0;
    #pragma unroll
    for (int r = 0; r < ROWS_PER_WARP; r++) {
        unsigned mask = __ballot_sync(0xffffffffu, cnt[r] != 0);
        int nt = __popc(mask);
        m = max(m, nt);
        int rl = warp * ROWS_PER_WARP + r;
        if (lane < NUM_CODES) {
            if (cnt[r]) {
                int pos = __popc(mask & lt);
                s_terms[rl * NUM_CODES + pos] =
                    make_int2(lane * (HIDDEN * 4), __float_as_int((float)cnt[r]));
            } else {
                unsigned zmask = ~mask & 0x3FFFFFu;
                int zpos = nt + __popc(zmask & lt);
                s_terms[rl * NUM_CODES + zpos] = make_int2(0, 0);   // pad: +0*emb[0]
            }
            int row = row_base + r;
            if (row < S) g_counts[row * NUM_CODES + lane] = 0;      // zero-restore
        }
    }
    __syncthreads();   // publishes s_emb (and own-warp s_terms)

    // ---- hot loop: 4 rows interleaved, uniform trip count m ----
    const char* const embb = (const char*)s_emb;
    const uint32_t lane_off = (uint32_t)lane << 4;
    const int2* t0 = &s_terms[(warp * ROWS_PER_WARP + 0) * NUM_CODES];
    const int2* t1 = &s_terms[(warp * ROWS_PER_WARP + 1) * NUM_CODES];
    const int2* t2 = &s_terms[(warp * ROWS_PER_WARP + 2) * NUM_CODES];
    const int2* t3 = &s_terms[(warp * ROWS_PER_WARP + 3) * NUM_CODES];

    float4 acc0 = make_float4(0.f,0.f,0.f,0.f), acc1 = acc0, acc2 = acc0, acc3 = acc0;

    for (int j = 0; j < m; j++) {
        int2 p0 = t0[j]; int2 p1 = t1[j]; int2 p2 = t2[j]; int2 p3 = t3[j];
        float4 e0 = *reinterpret_cast<const float4*>(embb + p0.x + lane_off);
        float4 e1 = *reinterpret_cast<const float4*>(embb + p1.x + lane_off);
        float4 e2 = *reinterpret_cast<const float4*>(embb + p2.x + lane_off);
        float4 e3 = *reinterpret_cast<const float4*>(embb + p3.x + lane_off);
        float f0 = __int_as_float(p0.y), f1 = __int_as_float(p1.y);
        float f2 = __int_as_float(p2.y), f3 = __int_as_float(p3.y);
        acc0.x += f0*e0.x; acc0.y += f0*e0.y; acc0.z += f0*e0.z; acc0.w += f0*e0.w;
        acc1.x += f1*e1.x; acc1.y += f1*e1.y; acc1.z += f1*e1.z; acc1.w += f1*e1.w;
        acc2.x += f2*e2.x; acc2.y += f2*e2.y; acc2.z += f2*e2.z; acc2.w += f2*e2.w;
        acc3.x += f3*e3.x; acc3.y += f3*e3.y; acc3.z += f3*e3.z; acc3.w += f3*e3.w;
    }

    float4* out4 = reinterpret_cast<float4*>(out);
    if (row_base + 0 < S) out4[(size_t)(row_base + 0) * 32 + lane] = acc0;
    if (row_base + 1 < S) out4[(size_t)(row_base + 1) * 32 + lane] = acc1;
    if (row_base + 2 < S) out4[(size_t)(row_base + 2) * 32 + lane] = acc2;
    if (row_base + 3 < S) out4[(size_t)(row_base + 3) * 32 + lane] = acc3;
}

extern "C" void kernel_launch(void* const* d_in, const int* in_sizes, int n_in,
                              void* d_out, int out_size)
{
    const int*   x   = (const int*)d_in[0];
    const int*   a2c = (const int*)d_in[1];
    const float* emb = (const float*)d_in[2];
    float*       out = (float*)d_out;

    const int E = in_sizes[1] / 2;                   // 600000
    const int S = out_size / HIDDEN;                 // 100000
    const int* atom_idx  = a2c;
    const int* cycle_idx = a2c + E;

    // 1) histogram edges into (cycle, code) counts, 8 edges/thread
    int E8 = E >> 3;
    if (E8 > 0)
        count_kernel<<<(E8 + 255) / 256, 256>>>(x, atom_idx, cycle_idx, E8);
    if (E & 7) {
        int start = E8 << 3, n = E - start;
        count_tail_kernel<<<(n + 255) / 256, 256>>>(x, atom_idx, cycle_idx, start, E);
    }

    // 2) expand counts -> output rows (32 rows/block); also re-zeros counts
    expand_kernel<<<(S + ROWS_PER_BLOCK - 1) / ROWS_PER_BLOCK, ETHREADS>>>(emb, out, S);
}